// round 11
// baseline (speedup 1.0000x reference)
#include <cuda_runtime.h>
#include <cstdint>
#include <cstddef>

#define NROWS 8192
#define ROW_F4 2048              // NROWS/4
#define ROW_SHIFT 11
#define NN_F4 (NROWS * (size_t)NROWS / 4)
#define CAP 256                  // per-row pos-list capacity (mean ~54, huge margin)

__device__ unsigned char g_cls[NROWS];
__device__ float2        g_rowp[NROWS];          // {ng, rv}
__device__ int           g_cnt[NROWS];           // per-row pos counters
__device__ int2          g_list[NROWS * CAP];    // {col, bitcast sigma}

// ---- one-block prolog: dtype probe + class bytes + histogram + row params
//      + zero pos counters. Runs in a few us. ----
__global__ __launch_bounds__(1024) void k_cls_hist(const int* __restrict__ w) {
    __shared__ int sh_hist[128];
    __shared__ int sh32;
    int t = threadIdx.x;
    if (t < 128) sh_hist[t] = 0;
    if (t == 0)  sh32 = 0;
    __syncthreads();
    // dtype probe, in-bounds for both dtypes (words < NROWS):
    // int64 values in [0,128) => odd 32-bit words zero; int32 => nonzero whp.
    if (t < 128 && w[2 * t + 1] != 0) sh32 = 1;
    __syncthreads();
    int is32 = sh32;

    // each thread handles 8 consecutive rows
    const int4* w4 = reinterpret_cast<const int4*>(w);
    unsigned char myc[8];
    if (is32) {
        int4 a = w4[2 * t], b = w4[2 * t + 1];
        myc[0]=(unsigned char)a.x; myc[1]=(unsigned char)a.y;
        myc[2]=(unsigned char)a.z; myc[3]=(unsigned char)a.w;
        myc[4]=(unsigned char)b.x; myc[5]=(unsigned char)b.y;
        myc[6]=(unsigned char)b.z; myc[7]=(unsigned char)b.w;
    } else {
        int4 a = w4[4 * t], b = w4[4 * t + 1], c = w4[4 * t + 2], d = w4[4 * t + 3];
        myc[0]=(unsigned char)a.x; myc[1]=(unsigned char)a.z;
        myc[2]=(unsigned char)b.x; myc[3]=(unsigned char)b.z;
        myc[4]=(unsigned char)c.x; myc[5]=(unsigned char)c.z;
        myc[6]=(unsigned char)d.x; myc[7]=(unsigned char)d.z;
    }
#pragma unroll
    for (int k = 0; k < 8; ++k) atomicAdd(&sh_hist[myc[k]], 1);
    // write class bytes (8 per thread, one uint2)
    uint2 packed;
    packed.x = (unsigned)myc[0] | ((unsigned)myc[1]<<8) | ((unsigned)myc[2]<<16) | ((unsigned)myc[3]<<24);
    packed.y = (unsigned)myc[4] | ((unsigned)myc[5]<<8) | ((unsigned)myc[6]<<16) | ((unsigned)myc[7]<<24);
    reinterpret_cast<uint2*>(g_cls)[t] = packed;
    // zero pos counters
#pragma unroll
    for (int k = 0; k < 8; ++k) g_cnt[t * 8 + k] = 0;
    __syncthreads();
    // per-row {ng, rv}
#pragma unroll
    for (int k = 0; k < 8; ++k) {
        int negraw = NROWS - sh_hist[myc[k]];
        float rv = (negraw > 0) ? 1.0f : 0.0f;
        float ng = 40.0f * rv / (float)((negraw > 1) ? negraw : 1);
        g_rowp[t * 8 + k] = make_float2(ng, rv);
    }
}

// ---- per-element math: loss + sigma(z); grad assembled by caller ----
__device__ __forceinline__ void elem(float simv, bool same, float rv,
                                     float& L, float& sg) {
    float s = simv - 0.5f;
    float z = same ? (-2.0f * s) : (40.0f * s);
    bool active = (!same) || (simv < 1.0f);
    float t   = __expf(-fabsf(z));
    float op  = 1.0f + t;
    float inv = __fdividef(1.0f, op);
    float sp  = fmaxf(z, 0.0f) + __logf(op);          // stable softplus(z)
    sg = ((z >= 0.0f) ? 1.0f : t) * inv;              // stable sigmoid(z)
    L = active ? sp * rv : 0.0f;
}

// ---- main streaming kernel (proven structure) + sparse pos append ----
__global__ __launch_bounds__(256) void k_main(const float* __restrict__ sim,
                                              float* __restrict__ out) {
    int idx  = blockIdx.x * blockDim.x + threadIdx.x;   // float4 index
    int row  = idx >> ROW_SHIFT;                        // block-uniform
    int col4 = idx & (ROW_F4 - 1);

    float4 sv = __ldcs(reinterpret_cast<const float4*>(sim) + idx);
    uchar4 cj = reinterpret_cast<const uchar4*>(g_cls)[col4];
    int    ci = g_cls[row];
    float2 p  = g_rowp[row];                            // {ng, rv}

    float4 Lo, Gr; float sg;
    bool s0 = (cj.x == ci), s1 = (cj.y == ci), s2 = (cj.z == ci), s3 = (cj.w == ci);

    elem(sv.x, s0, p.y, Lo.x, sg);
    Gr.x = s0 ? 0.0f : p.x * sg;
    if (s0 && sv.x < 1.0f) { int sl = atomicAdd(&g_cnt[row], 1);
        if (sl < CAP) g_list[row * CAP + sl] = make_int2(4 * col4 + 0, __float_as_int(sg)); }

    elem(sv.y, s1, p.y, Lo.y, sg);
    Gr.y = s1 ? 0.0f : p.x * sg;
    if (s1 && sv.y < 1.0f) { int sl = atomicAdd(&g_cnt[row], 1);
        if (sl < CAP) g_list[row * CAP + sl] = make_int2(4 * col4 + 1, __float_as_int(sg)); }

    elem(sv.z, s2, p.y, Lo.z, sg);
    Gr.z = s2 ? 0.0f : p.x * sg;
    if (s2 && sv.z < 1.0f) { int sl = atomicAdd(&g_cnt[row], 1);
        if (sl < CAP) g_list[row * CAP + sl] = make_int2(4 * col4 + 2, __float_as_int(sg)); }

    elem(sv.w, s3, p.y, Lo.w, sg);
    Gr.w = s3 ? 0.0f : p.x * sg;
    if (s3 && sv.w < 1.0f) { int sl = atomicAdd(&g_cnt[row], 1);
        if (sl < CAP) g_list[row * CAP + sl] = make_int2(4 * col4 + 3, __float_as_int(sg)); }

    float4* lossb = reinterpret_cast<float4*>(out);
    float4* gradb = lossb + NN_F4;
    __stcs(lossb + idx, Lo);
    __stcs(gradb + idx, Gr);
}

// ---- epilogue: scale + scatter the sparse pos grads ----
__global__ __launch_bounds__(256) void k_fix(float* __restrict__ out) {
    int wid  = threadIdx.x >> 5, lane = threadIdx.x & 31;
    int row  = blockIdx.x * 8 + wid;
    int cnt  = g_cnt[row];
    int lim  = (cnt < CAP) ? cnt : CAP;
    float rv = g_rowp[row].y;
    float pg = -2.0f * rv / (float)((cnt > 1) ? cnt : 1);
    float* gradrow = out + NROWS * (size_t)NROWS + (size_t)row * NROWS;
    for (int l = lane; l < lim; l += 32) {
        int2 e = g_list[row * CAP + l];
        gradrow[e.x] = pg * __int_as_float(e.y);
    }
}

extern "C" void kernel_launch(void* const* d_in, const int* in_sizes, int n_in,
                              void* d_out, int out_size) {
    const float* sim = (const float*)d_in[0];
    const int*   tgw = (const int*)d_in[1];     // int32 view of targets
    float*       out = (float*)d_out;

    k_cls_hist<<<1, 1024>>>(tgw);
    k_main<<<(int)(NN_F4 / 256), 256>>>(sim, out);
    k_fix<<<NROWS / 8, 256>>>(out);
}

// round 12
// speedup vs baseline: 1.3425x; 1.3425x over previous
#include <cuda_runtime.h>
#include <cstdint>
#include <cstddef>

#define NROWS 8192
#define ROW_F4 2048              // NROWS/4
#define ROW_SHIFT 11
#define NN_F4 (NROWS * (size_t)NROWS / 4)
#define CAP_M 256                // member-list capacity per class (mean 64, ~24 sigma)

__device__ unsigned char  g_cls[NROWS];
__device__ int            g_ctr[128];                 // per-class member counts
__device__ unsigned short g_mem[128 * CAP_M];         // member row indices per class
__device__ float4         g_params[NROWS];            // {pg, ng, rv, pad}

// ---- k_cls: dtype probe + class bytes + class-member lists (32 blocks) ----
// Dtype probe reads only words < NROWS (in-bounds for both dtypes): int64
// values in [0,128) => odd 32-bit words all zero; int32 => nonzero w.h.p.
__global__ __launch_bounds__(256) void k_cls(const int* __restrict__ w) {
    __shared__ int sh32;
    int t    = threadIdx.x;
    int base = blockIdx.x * 256;
    if (t == 0) sh32 = 0;
    if (base == 0 && t < 128) g_ctr[t] = 0;   // block 0 zeroes counters? NO: race with other blocks' atomics
    __syncthreads();
    if (t < 128 && w[2 * t + 1] != 0) sh32 = 1;
    __syncthreads();
    int i = base + t;
    int c = (sh32 ? w[i] : w[2 * i]) & 127;
    g_cls[i] = (unsigned char)c;
    int slot = atomicAdd(&g_ctr[c], 1);
    if (slot < CAP_M) g_mem[c * CAP_M + slot] = (unsigned short)i;
}

// zero counters must happen before k_cls's atomics: tiny separate kernel
__global__ void k_zero() { if (threadIdx.x < 128) g_ctr[threadIdx.x] = 0; }

// ---- k_prep: warp per row, dense member-list gather, NO scanning ----
__global__ __launch_bounds__(256) void k_prep(const float* __restrict__ sim) {
    int wid  = threadIdx.x >> 5, lane = threadIdx.x & 31;
    int row  = blockIdx.x * 8 + wid;
    int ci   = g_cls[row];
    int m    = g_ctr[ci];
    int lim  = (m < CAP_M) ? m : CAP_M;
    const float*          rowp = sim + (size_t)row * NROWS;
    const unsigned short* mem  = g_mem + ci * CAP_M;

    int pc = 0;
    for (int l = lane; l < lim; l += 32)
        pc += (rowp[mem[l]] < 1.0f) ? 1 : 0;      // includes diagonal, like reference
    pc = __reduce_add_sync(0xffffffffu, pc);

    if (lane == 0) {
        int negraw = NROWS - m;
        float rv = (negraw > 0) ? 1.0f : 0.0f;
        float pg = -2.0f * rv / (float)((pc     > 1) ? pc     : 1);
        float ng = 40.0f * rv / (float)((negraw > 1) ? negraw : 1);
        g_params[row] = make_float4(pg, ng, rv, 0.0f);
    }
}

// ---- per-element math ----
__device__ __forceinline__ void elem(float simv, bool same,
                                     float pg, float ng, float rv,
                                     float& L, float& G) {
    float s = simv - 0.5f;
    float z = same ? (-2.0f * s) : (40.0f * s);
    bool active = (!same) || (simv < 1.0f);
    float t   = __expf(-fabsf(z));
    float op  = 1.0f + t;
    float inv = __fdividef(1.0f, op);
    float sp  = fmaxf(z, 0.0f) + __logf(op);          // stable softplus(z)
    float sg  = ((z >= 0.0f) ? 1.0f : t) * inv;       // stable sigmoid(z)
    float cf  = same ? pg : ng;
    L = active ? sp * rv : 0.0f;
    G = active ? cf * sg : 0.0f;
}

// ---- main streaming kernel: PRISTINE R8 form (115.4us, 81% DRAM) ----
__global__ __launch_bounds__(256) void k_main(const float* __restrict__ sim,
                                              float* __restrict__ out) {
    int idx  = blockIdx.x * blockDim.x + threadIdx.x;   // float4 index
    int row  = idx >> ROW_SHIFT;
    int col4 = idx & (ROW_F4 - 1);

    float4 sv = __ldcs(reinterpret_cast<const float4*>(sim) + idx);
    uchar4 cj = reinterpret_cast<const uchar4*>(g_cls)[col4];
    int    ci = g_cls[row];
    float4 p  = g_params[row];

    float4 Lo, Gr;
    elem(sv.x, cj.x == ci, p.x, p.y, p.z, Lo.x, Gr.x);
    elem(sv.y, cj.y == ci, p.x, p.y, p.z, Lo.y, Gr.y);
    elem(sv.z, cj.z == ci, p.x, p.y, p.z, Lo.z, Gr.z);
    elem(sv.w, cj.w == ci, p.x, p.y, p.z, Lo.w, Gr.w);

    float4* lossb = reinterpret_cast<float4*>(out);
    float4* gradb = lossb + NN_F4;
    __stcs(lossb + idx, Lo);
    __stcs(gradb + idx, Gr);
}

extern "C" void kernel_launch(void* const* d_in, const int* in_sizes, int n_in,
                              void* d_out, int out_size) {
    const float* sim = (const float*)d_in[0];
    const int*   tgw = (const int*)d_in[1];     // int32 view of targets
    float*       out = (float*)d_out;

    k_zero<<<1, 128>>>();
    k_cls<<<NROWS / 256, 256>>>(tgw);
    k_prep<<<NROWS / 8, 256>>>(sim);
    k_main<<<(int)(NN_F4 / 256), 256>>>(sim, out);
}

// round 13
// speedup vs baseline: 1.3464x; 1.0029x over previous
#include <cuda_runtime.h>
#include <cstdint>
#include <cstddef>

#define NROWS 8192
#define ROW_F4 2048              // NROWS/4
#define ROW_SHIFT 11
#define NN_F4 (NROWS * (size_t)NROWS / 4)
#define CAP_M 256                // member-list capacity per class (mean 64, ~24 sigma)

// NOTE: g_ctr must be zero at entry to k_cls. It is zero-initialized at module
// load, and k_main re-zeroes it at the end of every call (k_main is stream-
// serialized after k_prep's reads), so the invariant holds across the
// correctness run and all graph replays.
__device__ unsigned char  g_cls[NROWS];
__device__ int            g_ctr[128];                 // per-class member counts
__device__ unsigned short g_mem[128 * CAP_M];         // member row indices per class
__device__ float4         g_params[NROWS];            // {pg, ng, rv, pad}

// ---- k_cls: dtype probe + class bytes + class-member lists (32 blocks) ----
// Dtype probe reads only words < NROWS (in-bounds for both dtypes): int64
// values in [0,128) => odd 32-bit words all zero; int32 => nonzero w.h.p.
__global__ __launch_bounds__(256) void k_cls(const int* __restrict__ w) {
    __shared__ int sh32;
    int t    = threadIdx.x;
    int base = blockIdx.x * 256;
    if (t == 0) sh32 = 0;
    __syncthreads();
    if (t < 128 && w[2 * t + 1] != 0) sh32 = 1;
    __syncthreads();
    int i = base + t;
    int c = (sh32 ? w[i] : w[2 * i]) & 127;
    g_cls[i] = (unsigned char)c;
    int slot = atomicAdd(&g_ctr[c], 1);
    if (slot < CAP_M) g_mem[c * CAP_M + slot] = (unsigned short)i;
}

// ---- k_prep: warp per row, dense member-list gather, NO scanning ----
__global__ __launch_bounds__(256) void k_prep(const float* __restrict__ sim) {
    int wid  = threadIdx.x >> 5, lane = threadIdx.x & 31;
    int row  = blockIdx.x * 8 + wid;
    int ci   = g_cls[row];
    int m    = g_ctr[ci];
    int lim  = (m < CAP_M) ? m : CAP_M;
    const float*          rowp = sim + (size_t)row * NROWS;
    const unsigned short* mem  = g_mem + ci * CAP_M;

    int pc = 0;
    for (int l = lane; l < lim; l += 32)
        pc += (rowp[mem[l]] < 1.0f) ? 1 : 0;      // includes diagonal, like reference
    pc = __reduce_add_sync(0xffffffffu, pc);

    if (lane == 0) {
        int negraw = NROWS - m;
        float rv = (negraw > 0) ? 1.0f : 0.0f;
        float pg = -2.0f * rv / (float)((pc     > 1) ? pc     : 1);
        float ng = 40.0f * rv / (float)((negraw > 1) ? negraw : 1);
        g_params[row] = make_float4(pg, ng, rv, 0.0f);
    }
}

// ---- per-element math ----
__device__ __forceinline__ void elem(float simv, bool same,
                                     float pg, float ng, float rv,
                                     float& L, float& G) {
    float s = simv - 0.5f;
    float z = same ? (-2.0f * s) : (40.0f * s);
    bool active = (!same) || (simv < 1.0f);
    float t   = __expf(-fabsf(z));
    float op  = 1.0f + t;
    float inv = __fdividef(1.0f, op);
    float sp  = fmaxf(z, 0.0f) + __logf(op);          // stable softplus(z)
    float sg  = ((z >= 0.0f) ? 1.0f : t) * inv;       // stable sigmoid(z)
    float cf  = same ? pg : ng;
    L = active ? sp * rv : 0.0f;
    G = active ? cf * sg : 0.0f;
}

// ---- main streaming kernel: PRISTINE R8 form (116us, 81% DRAM) ----
// Block 0 additionally re-zeroes g_ctr for the next call (runs after k_prep,
// so no reader remains; block-uniform branch, off the hot path).
__global__ __launch_bounds__(256) void k_main(const float* __restrict__ sim,
                                              float* __restrict__ out) {
    int idx  = blockIdx.x * blockDim.x + threadIdx.x;   // float4 index
    int row  = idx >> ROW_SHIFT;
    int col4 = idx & (ROW_F4 - 1);

    float4 sv = __ldcs(reinterpret_cast<const float4*>(sim) + idx);
    uchar4 cj = reinterpret_cast<const uchar4*>(g_cls)[col4];
    int    ci = g_cls[row];
    float4 p  = g_params[row];

    float4 Lo, Gr;
    elem(sv.x, cj.x == ci, p.x, p.y, p.z, Lo.x, Gr.x);
    elem(sv.y, cj.y == ci, p.x, p.y, p.z, Lo.y, Gr.y);
    elem(sv.z, cj.z == ci, p.x, p.y, p.z, Lo.z, Gr.z);
    elem(sv.w, cj.w == ci, p.x, p.y, p.z, Lo.w, Gr.w);

    float4* lossb = reinterpret_cast<float4*>(out);
    float4* gradb = lossb + NN_F4;
    __stcs(lossb + idx, Lo);
    __stcs(gradb + idx, Gr);

    if (blockIdx.x == 0 && threadIdx.x < 128) g_ctr[threadIdx.x] = 0;
}

extern "C" void kernel_launch(void* const* d_in, const int* in_sizes, int n_in,
                              void* d_out, int out_size) {
    const float* sim = (const float*)d_in[0];
    const int*   tgw = (const int*)d_in[1];     // int32 view of targets
    float*       out = (float*)d_out;

    k_cls<<<NROWS / 256, 256>>>(tgw);
    k_prep<<<NROWS / 8, 256>>>(sim);
    k_main<<<(int)(NN_F4 / 256), 256>>>(sim, out);
}

// round 14
// speedup vs baseline: 1.3584x; 1.0089x over previous
#include <cuda_runtime.h>
#include <cstdint>
#include <cstddef>

#define NROWS 8192
#define ROW_F4 2048              // NROWS/4
#define ROW_SHIFT 11
#define NN_F4 (NROWS * (size_t)NROWS / 4)
#define CAP_M 256                // member-list capacity per class (mean 64, ~24 sigma)

// g_ctr must be zero at entry to k_cls: zero-initialized at module load, and
// k_main re-zeroes it at the end of every call (stream-serialized after
// k_prep's reads), so the invariant holds across the correctness run and all
// graph replays.
__device__ unsigned char  g_cls[NROWS];
__device__ int            g_ctr[128];                 // per-class member counts
__device__ unsigned short g_mem[128 * CAP_M];         // member row indices per class
__device__ float4         g_params[NROWS];            // {pg, ng, rv, pad}

// ---- k_cls: dtype probe + class bytes + class-member lists (32 blocks) ----
// Dtype probe reads only words < NROWS (in-bounds for both dtypes): int64
// values in [0,128) => odd 32-bit words all zero; int32 => nonzero w.h.p.
__global__ __launch_bounds__(256) void k_cls(const int* __restrict__ w) {
    __shared__ int sh32;
    int t    = threadIdx.x;
    int base = blockIdx.x * 256;
    if (t == 0) sh32 = 0;
    __syncthreads();
    if (t < 128 && w[2 * t + 1] != 0) sh32 = 1;
    __syncthreads();
    int i = base + t;
    int c = (sh32 ? w[i] : w[2 * i]) & 127;
    g_cls[i] = (unsigned char)c;
    int slot = atomicAdd(&g_ctr[c], 1);
    if (slot < CAP_M) g_mem[c * CAP_M + slot] = (unsigned short)i;
}

// ---- k_prep: warp per row, dense member-list gather, NO scanning ----
// PDL secondary: wait for k_cls's writes before reading.
__global__ __launch_bounds__(256) void k_prep(const float* __restrict__ sim) {
    cudaGridDependencySynchronize();
    int wid  = threadIdx.x >> 5, lane = threadIdx.x & 31;
    int row  = blockIdx.x * 8 + wid;
    int ci   = g_cls[row];
    int m    = g_ctr[ci];
    int lim  = (m < CAP_M) ? m : CAP_M;
    const float*          rowp = sim + (size_t)row * NROWS;
    const unsigned short* mem  = g_mem + ci * CAP_M;

    int pc = 0;
    for (int l = lane; l < lim; l += 32)
        pc += (rowp[mem[l]] < 1.0f) ? 1 : 0;      // includes diagonal, like reference
    pc = __reduce_add_sync(0xffffffffu, pc);

    if (lane == 0) {
        int negraw = NROWS - m;
        float rv = (negraw > 0) ? 1.0f : 0.0f;
        float pg = -2.0f * rv / (float)((pc     > 1) ? pc     : 1);
        float ng = 40.0f * rv / (float)((negraw > 1) ? negraw : 1);
        g_params[row] = make_float4(pg, ng, rv, 0.0f);
    }
}

// ---- per-element math ----
__device__ __forceinline__ void elem(float simv, bool same,
                                     float pg, float ng, float rv,
                                     float& L, float& G) {
    float s = simv - 0.5f;
    float z = same ? (-2.0f * s) : (40.0f * s);
    bool active = (!same) || (simv < 1.0f);
    float t   = __expf(-fabsf(z));
    float op  = 1.0f + t;
    float inv = __fdividef(1.0f, op);
    float sp  = fmaxf(z, 0.0f) + __logf(op);          // stable softplus(z)
    float sg  = ((z >= 0.0f) ? 1.0f : t) * inv;       // stable sigmoid(z)
    float cf  = same ? pg : ng;
    L = active ? sp * rv : 0.0f;
    G = active ? cf * sg : 0.0f;
}

// ---- main streaming kernel: PRISTINE R8 hot path (116us, 81% DRAM) ----
// PDL secondary: wait for k_prep's params. Block 0 re-zeroes g_ctr at the end
// (runs after k_prep's reads; block-uniform branch, off the hot path).
__global__ __launch_bounds__(256) void k_main(const float* __restrict__ sim,
                                              float* __restrict__ out) {
    cudaGridDependencySynchronize();
    int idx  = blockIdx.x * blockDim.x + threadIdx.x;   // float4 index
    int row  = idx >> ROW_SHIFT;
    int col4 = idx & (ROW_F4 - 1);

    float4 sv = __ldcs(reinterpret_cast<const float4*>(sim) + idx);
    uchar4 cj = reinterpret_cast<const uchar4*>(g_cls)[col4];
    int    ci = g_cls[row];
    float4 p  = g_params[row];

    float4 Lo, Gr;
    elem(sv.x, cj.x == ci, p.x, p.y, p.z, Lo.x, Gr.x);
    elem(sv.y, cj.y == ci, p.x, p.y, p.z, Lo.y, Gr.y);
    elem(sv.z, cj.z == ci, p.x, p.y, p.z, Lo.z, Gr.z);
    elem(sv.w, cj.w == ci, p.x, p.y, p.z, Lo.w, Gr.w);

    float4* lossb = reinterpret_cast<float4*>(out);
    float4* gradb = lossb + NN_F4;
    __stcs(lossb + idx, Lo);
    __stcs(gradb + idx, Gr);

    if (blockIdx.x == 0 && threadIdx.x < 128) g_ctr[threadIdx.x] = 0;
}

extern "C" void kernel_launch(void* const* d_in, const int* in_sizes, int n_in,
                              void* d_out, int out_size) {
    const float* sim = (const float*)d_in[0];
    const int*   tgw = (const int*)d_in[1];     // int32 view of targets
    float*       out = (float*)d_out;

    k_cls<<<NROWS / 256, 256>>>(tgw);

    cudaLaunchAttribute attr[1];
    attr[0].id = cudaLaunchAttributeProgrammaticStreamSerialization;
    attr[0].val.programmaticStreamSerializationAllowed = 1;

    {
        cudaLaunchConfig_t cfg = {};
        cfg.gridDim  = dim3(NROWS / 8, 1, 1);
        cfg.blockDim = dim3(256, 1, 1);
        cfg.attrs    = attr;
        cfg.numAttrs = 1;
        cudaLaunchKernelEx(&cfg, k_prep, sim);
    }
    {
        cudaLaunchConfig_t cfg = {};
        cfg.gridDim  = dim3((unsigned)(NN_F4 / 256), 1, 1);
        cfg.blockDim = dim3(256, 1, 1);
        cfg.attrs    = attr;
        cfg.numAttrs = 1;
        cudaLaunchKernelEx(&cfg, k_main, sim, out);
    }
}